// round 1
// baseline (speedup 1.0000x reference)
#include <cuda_runtime.h>
#include <cuda_fp16.h>
#include <cstdint>
#include <cstddef>

#define EMB   128
#define NCL   256
#define NROWS 200000
#define NT    1563              // ceil(200000 / 128)
#define ROWS_PAD (NT * 128)     // 200064

// Static device scratch (allocation-free). Zero-initialized: pad rows stay 0.
__device__ __half g_xh[(size_t)ROWS_PAD * EMB];
__device__ float  g_xsq[ROWS_PAD];
__device__ __half g_ch[NCL * EMB];
__device__ float  g_csq[NCL];

// ---------------- prep kernels ----------------

__global__ void prep_clusters_kernel(const float* __restrict__ clusters) {
    int c = blockIdx.x;          // 256 blocks
    int d = threadIdx.x;         // 128 threads
    float v = clusters[c * EMB + d];
    g_ch[c * EMB + d] = __float2half_rn(v);
    float s = v * v;
    #pragma unroll
    for (int o = 16; o > 0; o >>= 1) s += __shfl_xor_sync(0xffffffffu, s, o);
    __shared__ float red[4];
    if ((d & 31) == 0) red[d >> 5] = s;
    __syncthreads();
    if (d == 0) g_csq[c] = red[0] + red[1] + red[2] + red[3];
}

__global__ void prep_inputs_kernel(const float* __restrict__ x) {
    int row  = blockIdx.x * 8 + (threadIdx.x >> 5);   // 8 warps/block, 1 row/warp
    int lane = threadIdx.x & 31;
    float4 v = reinterpret_cast<const float4*>(x)[(size_t)row * (EMB / 4) + lane];
    float s = v.x * v.x + v.y * v.y + v.z * v.z + v.w * v.w;
    #pragma unroll
    for (int o = 16; o > 0; o >>= 1) s += __shfl_xor_sync(0xffffffffu, s, o);
    if (lane == 0) g_xsq[row] = s;
    __half2 h0 = __floats2half2_rn(v.x, v.y);
    __half2 h1 = __floats2half2_rn(v.z, v.w);
    uint2 pk;
    pk.x = *reinterpret_cast<uint32_t*>(&h0);
    pk.y = *reinterpret_cast<uint32_t*>(&h1);
    reinterpret_cast<uint2*>(g_xh)[(size_t)row * (EMB / 4) + lane] = pk;
}

// ---------------- main kernel ----------------

__device__ __forceinline__ void cp16(uint32_t dst, const void* src) {
    asm volatile("cp.async.cg.shared.global [%0], [%1], 16;\n"
                 :: "r"(dst), "l"(src) : "memory");
}

__device__ __forceinline__ void mma16816(float* d, const uint32_t* a,
                                         uint32_t b0, uint32_t b1) {
    asm volatile(
        "mma.sync.aligned.m16n8k16.row.col.f32.f16.f16.f32 "
        "{%0,%1,%2,%3},{%4,%5,%6,%7},{%8,%9},{%0,%1,%2,%3};\n"
        : "+f"(d[0]), "+f"(d[1]), "+f"(d[2]), "+f"(d[3])
        : "r"(a[0]), "r"(a[1]), "r"(a[2]), "r"(a[3]), "r"(b0), "r"(b1));
}

// smem layout (dynamic):
//   B (clusters fp16, 256 rows x 136 halves = 272B stride) : [0, 69632)
//   A double buffer (128 rows x 272B each)                 : [69632, 139264)
//   rowsum (128 floats)                                    : [139264, 139776)
#define SMEM_B_OFF   0
#define SMEM_A_OFF   69632
#define A_BUF_BYTES  34816
#define SMEM_RS_OFF  139264
#define SMEM_TOTAL   139776

__global__ void __launch_bounds__(512, 1)
cluster_main_kernel(float* __restrict__ out) {
    extern __shared__ char smem[];
    const uint32_t sb = (uint32_t)__cvta_generic_to_shared(smem);
    const uint32_t sB = sb + SMEM_B_OFF;
    const uint32_t sA = sb + SMEM_A_OFF;
    float* rowsum = reinterpret_cast<float*>(smem + SMEM_RS_OFF);

    const int tid  = threadIdx.x;
    const int lane = tid & 31;
    const int wid  = tid >> 5;
    const int wm   = wid & 3;   // warp row 0..3 (32 rows each)
    const int wn   = wid >> 2;  // warp col 0..3 (64 cols each)

    // Load all clusters (fp16) into smem once. 4096 x 16B chunks.
    #pragma unroll
    for (int i = 0; i < 8; i++) {
        int c = tid + i * 512;
        int r = c >> 4, k = c & 15;
        cp16(sB + r * 272 + k * 16, g_ch + r * EMB + k * 8);
    }
    // First A tile (2048 x 16B chunks) into buffer 0.
    int tile = blockIdx.x;
    #pragma unroll
    for (int i = 0; i < 4; i++) {
        int c = tid + i * 512;
        int r = c >> 4, k = c & 15;
        cp16(sA + r * 272 + k * 16,
             g_xh + (size_t)(tile * 128 + r) * EMB + k * 8);
    }
    asm volatile("cp.async.commit_group;\n" ::: "memory");

    // Per-thread cluster-norm registers (columns fixed across tiles).
    float csA[8], csB[8];
    #pragma unroll
    for (int ni = 0; ni < 8; ni++) {
        int n0 = wn * 64 + ni * 8 + (lane & 3) * 2;
        csA[ni] = g_csq[n0];
        csB[ni] = g_csq[n0 + 1];
    }

    const uint32_t bRowBase = wn * 64 + (lane & 7) + ((lane >> 4) << 3);
    const uint32_t bColByte = ((lane >> 3) & 1) * 16;

    int buf = 0;
    for (; tile < NT; tile += gridDim.x) {
        int nxt = tile + gridDim.x;
        if (nxt < NT) {
            uint32_t sAn = sA + (buf ^ 1) * A_BUF_BYTES;
            #pragma unroll
            for (int i = 0; i < 4; i++) {
                int c = tid + i * 512;
                int r = c >> 4, k = c & 15;
                cp16(sAn + r * 272 + k * 16,
                     g_xh + (size_t)(nxt * 128 + r) * EMB + k * 8);
            }
            asm volatile("cp.async.commit_group;\n" ::: "memory");
            asm volatile("cp.async.wait_group 1;\n" ::: "memory");
        } else {
            asm volatile("cp.async.wait_group 0;\n" ::: "memory");
        }
        if (tid < 128) rowsum[tid] = 0.f;
        __syncthreads();   // A[buf] visible to all, rowsum zeroed

        const uint32_t sAc = sA + buf * A_BUF_BYTES;
        float acc[2][8][4];
        #pragma unroll
        for (int mi = 0; mi < 2; mi++)
            #pragma unroll
            for (int ni = 0; ni < 8; ni++)
                #pragma unroll
                for (int e = 0; e < 4; e++) acc[mi][ni][e] = 0.f;

        const uint32_t aAddrBase =
            sAc + (wm * 32 + (lane & 15)) * 272 + (lane >> 4) * 16;

        #pragma unroll
        for (int kk = 0; kk < 8; kk++) {
            uint32_t a[2][4];
            #pragma unroll
            for (int mi = 0; mi < 2; mi++) {
                uint32_t addr = aAddrBase + mi * (16 * 272) + kk * 32;
                asm volatile(
                    "ldmatrix.sync.aligned.m8n8.x4.shared.b16 {%0,%1,%2,%3},[%4];\n"
                    : "=r"(a[mi][0]), "=r"(a[mi][1]), "=r"(a[mi][2]), "=r"(a[mi][3])
                    : "r"(addr) : "memory");
            }
            #pragma unroll
            for (int nj = 0; nj < 4; nj++) {
                uint32_t b0, b1, b2, b3;
                uint32_t addr = sB + (bRowBase + nj * 16) * 272 + bColByte + kk * 32;
                asm volatile(
                    "ldmatrix.sync.aligned.m8n8.x4.shared.b16 {%0,%1,%2,%3},[%4];\n"
                    : "=r"(b0), "=r"(b1), "=r"(b2), "=r"(b3)
                    : "r"(addr) : "memory");
                #pragma unroll
                for (int mi = 0; mi < 2; mi++) {
                    mma16816(acc[mi][2 * nj],     a[mi], b0, b1);
                    mma16816(acc[mi][2 * nj + 1], a[mi], b2, b3);
                }
            }
        }
        __syncthreads();   // mma done (A[buf] free), orders rowsum-zero vs atomics

        // ---- fused epilogue: q = 1/(1 + max(||x||^2+||c||^2-2x.c, 0)) ----
        float onepx[2][2], part[2][2];
        #pragma unroll
        for (int mi = 0; mi < 2; mi++)
            #pragma unroll
            for (int h = 0; h < 2; h++) {
                int rl = wm * 32 + mi * 16 + (lane >> 2) + h * 8;
                onepx[mi][h] = 1.0f + g_xsq[tile * 128 + rl];
                part[mi][h] = 0.f;
            }
        #pragma unroll
        for (int mi = 0; mi < 2; mi++)
            #pragma unroll
            for (int ni = 0; ni < 8; ni++)
                #pragma unroll
                for (int h = 0; h < 2; h++) {
                    float d0 = fmaxf(fmaf(-2.f, acc[mi][ni][2 * h + 0],
                                          onepx[mi][h] + csA[ni]), 1.0f);
                    float d1 = fmaxf(fmaf(-2.f, acc[mi][ni][2 * h + 1],
                                          onepx[mi][h] + csB[ni]), 1.0f);
                    float q0, q1;
                    asm("rcp.approx.f32 %0, %1;\n" : "=f"(q0) : "f"(d0));
                    asm("rcp.approx.f32 %0, %1;\n" : "=f"(q1) : "f"(d1));
                    acc[mi][ni][2 * h + 0] = q0;
                    acc[mi][ni][2 * h + 1] = q1;
                    part[mi][h] += q0 + q1;
                }
        #pragma unroll
        for (int mi = 0; mi < 2; mi++)
            #pragma unroll
            for (int h = 0; h < 2; h++) {
                float s = part[mi][h];
                s += __shfl_xor_sync(0xffffffffu, s, 1);
                s += __shfl_xor_sync(0xffffffffu, s, 2);
                if ((lane & 3) == 0) {
                    int rl = wm * 32 + mi * 16 + (lane >> 2) + h * 8;
                    atomicAdd(&rowsum[rl], s);
                }
            }
        __syncthreads();   // rowsum complete

        #pragma unroll
        for (int mi = 0; mi < 2; mi++)
            #pragma unroll
            for (int h = 0; h < 2; h++) {
                int rl   = wm * 32 + mi * 16 + (lane >> 2) + h * 8;
                int grow = tile * 128 + rl;
                if (grow < NROWS) {
                    float inv;
                    asm("rcp.approx.f32 %0, %1;\n" : "=f"(inv) : "f"(rowsum[rl]));
                    float* op = out + (size_t)grow * NCL + wn * 64 + (lane & 3) * 2;
                    #pragma unroll
                    for (int ni = 0; ni < 8; ni++) {
                        float2 v = make_float2(acc[mi][ni][2 * h + 0] * inv,
                                               acc[mi][ni][2 * h + 1] * inv);
                        *reinterpret_cast<float2*>(op + ni * 8) = v;
                    }
                }
            }
        buf ^= 1;
    }
}

// ---------------- launcher ----------------

extern "C" void kernel_launch(void* const* d_in, const int* in_sizes, int n_in,
                              void* d_out, int out_size) {
    const float* x  = (const float*)d_in[0];
    const float* cl = (const float*)d_in[1];
    if (n_in >= 2 && in_sizes[0] == NCL * EMB) {  // defensive input-order check
        const float* t = x; x = cl; cl = t;
    }
    float* out = (float*)d_out;

    prep_clusters_kernel<<<NCL, 128>>>(cl);
    prep_inputs_kernel<<<NROWS / 8, 256>>>(x);

    int sms = 148, dev = 0;
    if (cudaGetDevice(&dev) == cudaSuccess) {
        int v = 0;
        if (cudaDeviceGetAttribute(&v, cudaDevAttrMultiProcessorCount, dev) == cudaSuccess
            && v > 0) sms = v;
    }
    cudaFuncSetAttribute(cluster_main_kernel,
                         cudaFuncAttributeMaxDynamicSharedMemorySize, SMEM_TOTAL);
    cluster_main_kernel<<<sms, 512, SMEM_TOTAL>>>(out);
}

// round 2
// speedup vs baseline: 1.2763x; 1.2763x over previous
#include <cuda_runtime.h>
#include <cuda_fp16.h>
#include <cstdint>
#include <cstddef>

#define EMB   128
#define NCL   256
#define NROWS 200000
#define NT    1563              // ceil(200000 / 128)

// ---- smem layout (bytes) ----
//   B   : clusters fp16, 256 rows x 272B stride      [0,      69632)
//   A   : X fp16 double buffer, 128 rows x 272B each [69632, 139264)
//   STG : fp32 staging, 128 rows x 512B (swizzled)   [139264, 204800)
//   RS  : rowsum, 128 f32                            [204800, 205312)
//   XSQ : row norms, 2 x 128 f32                     [205312, 206336)
//   CSQ : cluster norms, 256 f32                     [206336, 207360)
#define SB_OFF     0
#define SA_OFF     69632
#define A_BUF      34816
#define STG_OFF    139264
#define RS_OFF     204800
#define XSQ_OFF    205312
#define CSQ_OFF    206336
#define SMEM_TOTAL 207360

// staging address of 16B chunk g (0..31) of row r: XOR swizzle keeps both the
// cp.async stores and the strided float4 LDS (g = 4j + s) conflict-free.
__device__ __forceinline__ uint32_t stg_addr(uint32_t stg, int r, int g) {
    return stg + r * 512 + ((g ^ ((r & 7) << 2)) << 4);
}

__device__ __forceinline__ void cp16z(uint32_t dst, const void* src, int pbytes) {
    asm volatile("cp.async.cg.shared.global [%0], [%1], 16, %2;\n"
                 :: "r"(dst), "l"(src), "r"(pbytes) : "memory");
}

__device__ __forceinline__ void mma16816(float* d, const uint32_t* a,
                                         uint32_t b0, uint32_t b1) {
    asm volatile(
        "mma.sync.aligned.m16n8k16.row.col.f32.f16.f16.f32 "
        "{%0,%1,%2,%3},{%4,%5,%6,%7},{%8,%9},{%0,%1,%2,%3};\n"
        : "+f"(d[0]), "+f"(d[1]), "+f"(d[2]), "+f"(d[3])
        : "r"(a[0]), "r"(a[1]), "r"(a[2]), "r"(a[3]), "r"(b0), "r"(b1));
}

// Stage one 128-row fp32 tile into the swizzled staging buffer.
// Thread tid owns row r = tid>>2, chunks g = 4j + (tid&3). Rows past NROWS
// are zero-filled (src-size 0) and the pointer clamped so it is never formed OOB.
__device__ __forceinline__ void stage_tile(uint32_t stg, const float* __restrict__ x,
                                           int tt, int tid) {
    int r = tid >> 2, s = tid & 3;
    int grow = tt * 128 + r;
    int pb = (grow < NROWS) ? 16 : 0;
    int crow = (grow < NROWS) ? grow : (NROWS - 1);
    const float* src = x + (size_t)crow * EMB;
    #pragma unroll
    for (int j = 0; j < 8; j++) {
        int g = 4 * j + s;
        cp16z(stg_addr(stg, r, g), src + g * 4, pb);
    }
}

// Convert staged fp32 tile -> fp16 A buffer; also compute per-row ||x||^2.
__device__ __forceinline__ void convert_tile(char* smem, int dstbuf, int tid,
                                             float* __restrict__ xsq_dst) {
    int r = tid >> 2, s = tid & 3;
    const char* stg = smem + STG_OFF;
    char* a = smem + SA_OFF + dstbuf * A_BUF + r * 272;
    float acc = 0.f;
    #pragma unroll
    for (int j = 0; j < 8; j++) {
        int g = 4 * j + s;
        int so = r * 512 + ((g ^ ((r & 7) << 2)) << 4);
        float4 f = *reinterpret_cast<const float4*>(stg + so);
        acc += f.x * f.x + f.y * f.y + f.z * f.z + f.w * f.w;
        __half2 h0 = __floats2half2_rn(f.x, f.y);
        __half2 h1 = __floats2half2_rn(f.z, f.w);
        uint2 pk;
        pk.x = *reinterpret_cast<uint32_t*>(&h0);
        pk.y = *reinterpret_cast<uint32_t*>(&h1);
        *reinterpret_cast<uint2*>(a + g * 8) = pk;
    }
    acc += __shfl_xor_sync(0xffffffffu, acc, 1);
    acc += __shfl_xor_sync(0xffffffffu, acc, 2);
    if (s == 0) xsq_dst[r] = acc;
}

__global__ void __launch_bounds__(512, 1)
cluster_fused_kernel(const float* __restrict__ x, const float* __restrict__ cl,
                     float* __restrict__ out) {
    extern __shared__ char smem[];
    const uint32_t sb   = (uint32_t)__cvta_generic_to_shared(smem);
    const uint32_t sB   = sb + SB_OFF;
    const uint32_t sA   = sb + SA_OFF;
    const uint32_t sSTG = sb + STG_OFF;
    float* rowsum = reinterpret_cast<float*>(smem + RS_OFF);
    float* xsq_s  = reinterpret_cast<float*>(smem + XSQ_OFF);   // [2][128]
    float* csq_s  = reinterpret_cast<float*>(smem + CSQ_OFF);   // [256]

    const int tid  = threadIdx.x;
    const int lane = tid & 31;
    const int wid  = tid >> 5;
    const int wm   = wid & 3;   // warp row 0..3 (32 rows each)
    const int wn   = wid >> 2;  // warp col 0..3 (64 cols each)
    const int grid = gridDim.x;

    int tile = blockIdx.x;

    // ---- prologue: stage tile0 (async), convert clusters meanwhile ----
    stage_tile(sSTG, x, tile, tid);
    asm volatile("cp.async.commit_group;\n" ::: "memory");

    {   // clusters fp32 -> fp16 smem B (272B row stride) + ||c||^2
        int row = tid >> 1, half = tid & 1;
        const float4* src = reinterpret_cast<const float4*>(cl + row * EMB + half * 64);
        char* b = smem + SB_OFF + row * 272 + half * 128;
        float s = 0.f;
        #pragma unroll
        for (int c = 0; c < 16; c++) {
            float4 f = src[c];
            s += f.x * f.x + f.y * f.y + f.z * f.z + f.w * f.w;
            __half2 h0 = __floats2half2_rn(f.x, f.y);
            __half2 h1 = __floats2half2_rn(f.z, f.w);
            uint2 pk;
            pk.x = *reinterpret_cast<uint32_t*>(&h0);
            pk.y = *reinterpret_cast<uint32_t*>(&h1);
            *reinterpret_cast<uint2*>(b + c * 8) = pk;
        }
        s += __shfl_xor_sync(0xffffffffu, s, 1);
        if (half == 0) csq_s[row] = s;
    }

    asm volatile("cp.async.wait_group 0;\n" ::: "memory");
    convert_tile(smem, 0, tid, xsq_s);          // tile0 -> A[0], xsq[0]
    if (tile + grid < NT) {
        stage_tile(sSTG, x, tile + grid, tid);
        asm volatile("cp.async.commit_group;\n" ::: "memory");
    }
    __syncthreads();    // B, csq, A[0], xsq[0] visible

    // Per-thread cluster-norm registers (columns fixed across tiles).
    float csA[8], csB[8];
    #pragma unroll
    for (int ni = 0; ni < 8; ni++) {
        int n0 = wn * 64 + ni * 8 + (lane & 3) * 2;
        csA[ni] = csq_s[n0];
        csB[ni] = csq_s[n0 + 1];
    }

    const uint32_t bRowBase = wn * 64 + (lane & 7) + ((lane >> 4) << 3);
    const uint32_t bColByte = ((lane >> 3) & 1) * 16;

    int buf = 0;
    for (; tile < NT; tile += grid) {
        if (tid < 128) rowsum[tid] = 0.f;
        __syncthreads();   // S1: rowsum zeroed; prev conversion's A visible

        // ---- MMA on A[buf] ----
        const uint32_t sAc = sA + buf * A_BUF;
        float acc[2][8][4];
        #pragma unroll
        for (int mi = 0; mi < 2; mi++)
            #pragma unroll
            for (int ni = 0; ni < 8; ni++)
                #pragma unroll
                for (int e = 0; e < 4; e++) acc[mi][ni][e] = 0.f;

        const uint32_t aAddrBase =
            sAc + (wm * 32 + (lane & 15)) * 272 + (lane >> 4) * 16;

        #pragma unroll
        for (int kk = 0; kk < 8; kk++) {
            uint32_t a[2][4];
            #pragma unroll
            for (int mi = 0; mi < 2; mi++) {
                uint32_t addr = aAddrBase + mi * (16 * 272) + kk * 32;
                asm volatile(
                    "ldmatrix.sync.aligned.m8n8.x4.shared.b16 {%0,%1,%2,%3},[%4];\n"
                    : "=r"(a[mi][0]), "=r"(a[mi][1]), "=r"(a[mi][2]), "=r"(a[mi][3])
                    : "r"(addr) : "memory");
            }
            #pragma unroll
            for (int nj = 0; nj < 4; nj++) {
                uint32_t b0, b1, b2, b3;
                uint32_t addr = sB + (bRowBase + nj * 16) * 272 + bColByte + kk * 32;
                asm volatile(
                    "ldmatrix.sync.aligned.m8n8.x4.shared.b16 {%0,%1,%2,%3},[%4];\n"
                    : "=r"(b0), "=r"(b1), "=r"(b2), "=r"(b3)
                    : "r"(addr) : "memory");
                #pragma unroll
                for (int mi = 0; mi < 2; mi++) {
                    mma16816(acc[mi][2 * nj],     a[mi], b0, b1);
                    mma16816(acc[mi][2 * nj + 1], a[mi], b2, b3);
                }
            }
        }

        // ---- pipeline: convert next tile (A[buf^1]) & stage tile after next ----
        int nxt = tile + grid;
        if (nxt < NT) {
            asm volatile("cp.async.wait_group 0;\n" ::: "memory");
            convert_tile(smem, buf ^ 1, tid, xsq_s + (buf ^ 1) * 128);
            int nn = nxt + grid;
            if (nn < NT) {
                stage_tile(sSTG, x, nn, tid);
                asm volatile("cp.async.commit_group;\n" ::: "memory");
            }
        }

        // ---- fused epilogue: q = 1/(1 + max(||x||^2+||c||^2-2x.c, 0)) ----
        const float* xsq_cur = xsq_s + buf * 128;
        float onepx[2][2], part[2][2];
        #pragma unroll
        for (int mi = 0; mi < 2; mi++)
            #pragma unroll
            for (int h = 0; h < 2; h++) {
                int rl = wm * 32 + mi * 16 + (lane >> 2) + h * 8;
                onepx[mi][h] = 1.0f + xsq_cur[rl];
                part[mi][h] = 0.f;
            }
        #pragma unroll
        for (int mi = 0; mi < 2; mi++)
            #pragma unroll
            for (int ni = 0; ni < 8; ni++)
                #pragma unroll
                for (int h = 0; h < 2; h++) {
                    float d0 = fmaxf(fmaf(-2.f, acc[mi][ni][2 * h + 0],
                                          onepx[mi][h] + csA[ni]), 1.0f);
                    float d1 = fmaxf(fmaf(-2.f, acc[mi][ni][2 * h + 1],
                                          onepx[mi][h] + csB[ni]), 1.0f);
                    float q0, q1;
                    asm("rcp.approx.f32 %0, %1;\n" : "=f"(q0) : "f"(d0));
                    asm("rcp.approx.f32 %0, %1;\n" : "=f"(q1) : "f"(d1));
                    acc[mi][ni][2 * h + 0] = q0;
                    acc[mi][ni][2 * h + 1] = q1;
                    part[mi][h] += q0 + q1;
                }
        #pragma unroll
        for (int mi = 0; mi < 2; mi++)
            #pragma unroll
            for (int h = 0; h < 2; h++) {
                float s = part[mi][h];
                s += __shfl_xor_sync(0xffffffffu, s, 1);
                s += __shfl_xor_sync(0xffffffffu, s, 2);
                if ((lane & 3) == 0) {
                    int rl = wm * 32 + mi * 16 + (lane >> 2) + h * 8;
                    atomicAdd(&rowsum[rl], s);
                }
            }
        __syncthreads();   // S2: rowsum complete

        #pragma unroll
        for (int mi = 0; mi < 2; mi++)
            #pragma unroll
            for (int h = 0; h < 2; h++) {
                int rl   = wm * 32 + mi * 16 + (lane >> 2) + h * 8;
                int grow = tile * 128 + rl;
                if (grow < NROWS) {
                    float inv;
                    asm("rcp.approx.f32 %0, %1;\n" : "=f"(inv) : "f"(rowsum[rl]));
                    float* op = out + (size_t)grow * NCL + wn * 64 + (lane & 3) * 2;
                    #pragma unroll
                    for (int ni = 0; ni < 8; ni++) {
                        float2 v = make_float2(acc[mi][ni][2 * h + 0] * inv,
                                               acc[mi][ni][2 * h + 1] * inv);
                        *reinterpret_cast<float2*>(op + ni * 8) = v;
                    }
                }
            }
        __syncthreads();   // S3: rowsum reads done before next zeroing
        buf ^= 1;
    }
}

// ---------------- launcher ----------------

extern "C" void kernel_launch(void* const* d_in, const int* in_sizes, int n_in,
                              void* d_out, int out_size) {
    const float* x  = (const float*)d_in[0];
    const float* cl = (const float*)d_in[1];
    if (n_in >= 2 && in_sizes[0] == NCL * EMB) {  // defensive input-order check
        const float* t = x; x = cl; cl = t;
    }
    float* out = (float*)d_out;

    int sms = 148, dev = 0;
    if (cudaGetDevice(&dev) == cudaSuccess) {
        int v = 0;
        if (cudaDeviceGetAttribute(&v, cudaDevAttrMultiProcessorCount, dev) == cudaSuccess
            && v > 0) sms = v;
    }
    cudaFuncSetAttribute(cluster_fused_kernel,
                         cudaFuncAttributeMaxDynamicSharedMemorySize, SMEM_TOTAL);
    cluster_fused_kernel<<<sms, 512, SMEM_TOTAL>>>(x, cl, out);
}